// round 14
// baseline (speedup 1.0000x reference)
#include <cuda_runtime.h>
#include <mma.h>

using namespace nvcuda;

#define N_MAX 50000
#define E_MAX 800000

// Scratch (allocation-free rule: __device__ globals)
__device__ float g_h[(size_t)E_MAX * 64];   // per-edge MLP output, CSR-permuted
__device__ float g_agg[N_MAX * 64];         // per-node mean
__device__ int g_deg[N_MAX];
__device__ int g_off[N_MAX];
__device__ int g_fill[N_MAX];
__device__ int g_pos[E_MAX];
__device__ int g_row[E_MAX];
__device__ int g_col[E_MAX];
__device__ int g_is32;

// ---------------------------------------------------------------------------
__device__ __forceinline__ float lrelu(float v) { return v > 0.f ? v : 0.01f * v; }

__device__ __forceinline__ float to_tf32(float v) {
    unsigned o;
    asm("cvt.rna.tf32.f32 %0, %1;" : "=r"(o) : "f"(v));
    return __uint_as_float(o);
}

// ---------------------------------------------------------------------------
// Prep kernels
// ---------------------------------------------------------------------------
__global__ void zero_kernel(int N) {
    int i = blockIdx.x * blockDim.x + threadIdx.x;
    int stride = gridDim.x * blockDim.x;
    if (i == 0) g_is32 = 0;
    for (int j = i; j < N; j += stride) g_deg[j] = 0;
}

__global__ void detect_kernel(const long long* __restrict__ ei64, int E, int N) {
    int i = blockIdx.x * blockDim.x + threadIdx.x;
    int stride = gridDim.x * blockDim.x;
    int bad = 0;
    for (int j = i; j < E; j += stride) {
        long long v = ei64[j];
        if (v < 0 || v >= (long long)N) bad = 1;
    }
    if (__ballot_sync(0xffffffffu, bad) && (threadIdx.x & 31) == 0)
        atomicOr(&g_is32, 1);
}

__global__ void convert_kernel(const void* __restrict__ eiraw, int E, int N) {
    int i = blockIdx.x * blockDim.x + threadIdx.x;
    int stride = gridDim.x * blockDim.x;
    int is32 = g_is32;
    if (is32) {
        const int* p = (const int*)eiraw;
        for (int j = i; j < E; j += stride) {
            int c = min(max(p[E + j], 0), N - 1);
            g_row[j] = min(max(p[j], 0), N - 1);
            g_col[j] = c;
            atomicAdd(&g_deg[c], 1);
        }
    } else {
        const long long* p = (const long long*)eiraw;
        for (int j = i; j < E; j += stride) {
            int c = min(max((int)p[E + j], 0), N - 1);
            g_row[j] = min(max((int)p[j], 0), N - 1);
            g_col[j] = c;
            atomicAdd(&g_deg[c], 1);
        }
    }
}

// Single-block exclusive prefix scan over g_deg -> g_off (and g_fill copy).
__global__ __launch_bounds__(1024, 1) void scan_kernel(int N) {
    __shared__ int wsum[32];
    int tid = threadIdx.x, lane = tid & 31, wid = tid >> 5;
    int CH = (N + 1023) >> 10;
    int base = tid * CH;
    int local = 0;
    for (int j = 0; j < CH; j++) {
        int idx = base + j;
        if (idx < N) local += g_deg[idx];
    }
    int v = local;
#pragma unroll
    for (int o = 1; o < 32; o <<= 1) {
        int t = __shfl_up_sync(0xffffffffu, v, o);
        if (lane >= o) v += t;
    }
    if (lane == 31) wsum[wid] = v;
    __syncthreads();
    if (wid == 0) {
        int s = wsum[lane];
#pragma unroll
        for (int o = 1; o < 32; o <<= 1) {
            int t = __shfl_up_sync(0xffffffffu, s, o);
            if (lane >= o) s += t;
        }
        wsum[lane] = s;
    }
    __syncthreads();
    int run = v - local + (wid > 0 ? wsum[wid - 1] : 0);
    for (int j = 0; j < CH; j++) {
        int idx = base + j;
        if (idx < N) {
            g_off[idx] = run;
            g_fill[idx] = run;
            run += g_deg[idx];
        }
    }
}

__global__ void fill_kernel(int E) {
    int i = blockIdx.x * blockDim.x + threadIdx.x;
    int stride = gridDim.x * blockDim.x;
    for (int j = i; j < E; j += stride)
        g_pos[j] = atomicAdd(&g_fill[g_col[j]], 1);
}

// Per-node mean over the contiguous CSR segment of g_h. One warp per node.
__global__ void agg_kernel(int N) {
    int gw = (blockIdx.x * blockDim.x + threadIdx.x) >> 5;
    int lane = threadIdx.x & 31;
    int nw = (gridDim.x * blockDim.x) >> 5;
    for (int n = gw; n < N; n += nw) {
        int s = g_off[n], deg = g_deg[n];
        float ax = 0.f, ay = 0.f;
        for (int j = 0; j < deg; j++) {
            float2 v = ((const float2*)(g_h + (size_t)(s + j) * 64))[lane];
            ax += v.x;
            ay += v.y;
        }
        float inv = 1.f / fmaxf((float)deg, 1.f);
        ((float2*)(g_agg + (size_t)n * 64))[lane] = make_float2(ax * inv, ay * inv);
    }
}

// ---------------------------------------------------------------------------
#define LDA 136

// Edge M-tile=128 layer: warp (rt, nh) computes rows rt*32..+31, cols
// (nh*NT*16)..; 2xNT fragments. Bias broadcast via ldm=0 accumulator load.
template <int KS, int NT, bool TF32OUT>
__device__ __forceinline__ void mlp_layer128(const float* __restrict__ Ab,
                                             const float* __restrict__ W, int ldw,
                                             const float* __restrict__ biasRow,
                                             float* __restrict__ Ao,
                                             int rt, int nh) {
    wmma::fragment<wmma::accumulator, 16, 16, 8, float> acc[2][NT];
#pragma unroll
    for (int mt = 0; mt < 2; mt++)
#pragma unroll
        for (int nt = 0; nt < NT; nt++)
            wmma::load_matrix_sync(acc[mt][nt], biasRow + (nh * NT + nt) * 16, 0,
                                   wmma::mem_row_major);
#pragma unroll
    for (int ks = 0; ks < KS; ks++) {
        wmma::fragment<wmma::matrix_a, 16, 16, 8, wmma::precision::tf32,
                       wmma::row_major> af[2];
#pragma unroll
        for (int mt = 0; mt < 2; mt++)
            wmma::load_matrix_sync(af[mt], Ab + (rt * 32 + mt * 16) * LDA + ks * 8, LDA);
        wmma::fragment<wmma::matrix_b, 16, 16, 8, wmma::precision::tf32,
                       wmma::row_major> bf[NT];
#pragma unroll
        for (int nt = 0; nt < NT; nt++)
            wmma::load_matrix_sync(bf[nt], W + ks * 8 * ldw + (nh * NT + nt) * 16, ldw);
#pragma unroll
        for (int mt = 0; mt < 2; mt++)
#pragma unroll
            for (int nt = 0; nt < NT; nt++)
                wmma::mma_sync(acc[mt][nt], af[mt], bf[nt], acc[mt][nt]);
    }
    __syncthreads();  // all reads of A done before overwrite
#pragma unroll
    for (int mt = 0; mt < 2; mt++)
#pragma unroll
        for (int nt = 0; nt < NT; nt++) {
#pragma unroll
            for (int i = 0; i < acc[mt][nt].num_elements; i++) {
                float v = lrelu(acc[mt][nt].x[i]);
                acc[mt][nt].x[i] = TF32OUT ? to_tf32(v) : v;
            }
            wmma::store_matrix_sync(Ao + (rt * 32 + mt * 16) * LDA + (nh * NT + nt) * 16,
                                    acc[mt][nt], LDA, wmma::mem_row_major);
        }
    __syncthreads();
}

// ---------------------------------------------------------------------------
// Edge kernel: M-tile=128, 512 threads = 16 warps (4 rt x 4 nh).
// SMEM: A[128][136] | W0[96][136] | W1[128][136] | W2[128][72] | biases
#define E_A 0
#define E_W0 69632
#define E_W1 121856
#define E_W2 191488
#define E_BS 228352
#define E_SM 230144

__global__ __launch_bounds__(512, 1)
void edge_tc(const float* __restrict__ x, const float* __restrict__ ea,
             const float* __restrict__ w0g, const float* __restrict__ b0g,
             const float* __restrict__ w1g, const float* __restrict__ b1g,
             const float* __restrict__ w2g, const float* __restrict__ b2g,
             const float* __restrict__ gg, const float* __restrict__ btg, int E) {
    extern __shared__ char sm[];
    float* A = (float*)(sm + E_A);
    float* W0 = (float*)(sm + E_W0);
    float* W1 = (float*)(sm + E_W1);
    float* W2 = (float*)(sm + E_W2);
    float* BS = (float*)(sm + E_BS);  // b0[128] b1[128] b2[64] g[64] beta[64]
    float* B0 = BS, *B1 = BS + 128, *B2 = BS + 256, *LNg = BS + 320, *LNb = BS + 384;

    int tid = threadIdx.x;
    for (int i = tid; i < 96 * 128; i += 512) {
        int k = i >> 7, n = i & 127;
        W0[k * LDA + n] = to_tf32(w0g[i]);
    }
    for (int i = tid; i < 128 * 128; i += 512) {
        int k = i >> 7, n = i & 127;
        W1[k * LDA + n] = to_tf32(w1g[i]);
    }
    for (int i = tid; i < 128 * 64; i += 512) {
        int k = i >> 6, n = i & 63;
        W2[k * 72 + n] = to_tf32(w2g[i]);
    }
    if (tid < 128) { B0[tid] = b0g[tid]; B1[tid] = b1g[tid]; }
    if (tid < 64) { B2[tid] = b2g[tid]; LNg[tid] = gg[tid]; LNb[tid] = btg[tid]; }
    __syncthreads();

    int warp = tid >> 5;
    int rt = warp & 3, nh = warp >> 2;
    int r = tid >> 2, seg = tid & 3;  // gather/LN role: 4 threads per row
    int ntiles = (E + 127) >> 7;

    for (int gi = blockIdx.x; gi < ntiles; gi += gridDim.x) {
        int e = (gi << 7) + r;
        bool ok = e < E;
        // ---- Gather: row r, 96 cols (x[row] 64 ++ ea 32), 6 float4/thread
        {
            int rw = ok ? g_row[e] : 0;
            const float4* xp = (const float4*)(x + (size_t)rw * 64);
            const float4* ep = (const float4*)(ea + (size_t)e * 32);
#pragma unroll
            for (int j = 0; j < 6; j++) {
                int q = seg * 6 + j;
                float4 v = ok ? (q < 16 ? __ldg(xp + q) : __ldg(ep + (q - 16)))
                              : make_float4(0.f, 0.f, 0.f, 0.f);
                float4 o = make_float4(to_tf32(v.x), to_tf32(v.y),
                                       to_tf32(v.z), to_tf32(v.w));
                *(float4*)(A + r * LDA + q * 4) = o;
            }
        }
        __syncthreads();
        // ---- 3 layers (N=128,128,64)
        mlp_layer128<12, 2, true>(A, W0, LDA, B0, A, rt, nh);
        mlp_layer128<16, 2, true>(A, W1, LDA, B1, A, rt, nh);
        mlp_layer128<16, 1, false>(A, W2, 72, B2, A, rt, nh);
        // ---- LayerNorm per row + plain store to CSR slot (NO atomics)
        {
            float4 v0 = *(float4*)(A + r * LDA + seg * 16);
            float4 v1 = *(float4*)(A + r * LDA + seg * 16 + 4);
            float4 v2 = *(float4*)(A + r * LDA + seg * 16 + 8);
            float4 v3 = *(float4*)(A + r * LDA + seg * 16 + 12);
            float s = v0.x + v0.y + v0.z + v0.w + v1.x + v1.y + v1.z + v1.w +
                      v2.x + v2.y + v2.z + v2.w + v3.x + v3.y + v3.z + v3.w;
#pragma unroll
            for (int off = 2; off; off >>= 1) s += __shfl_xor_sync(0xffffffffu, s, off);
            float mu = s * (1.f / 64.f);
            float d[16] = {v0.x - mu, v0.y - mu, v0.z - mu, v0.w - mu,
                           v1.x - mu, v1.y - mu, v1.z - mu, v1.w - mu,
                           v2.x - mu, v2.y - mu, v2.z - mu, v2.w - mu,
                           v3.x - mu, v3.y - mu, v3.z - mu, v3.w - mu};
            float q = 0.f;
#pragma unroll
            for (int j = 0; j < 16; j++) q += d[j] * d[j];
#pragma unroll
            for (int off = 2; off; off >>= 1) q += __shfl_xor_sync(0xffffffffu, q, off);
            float rs = rsqrtf(q * (1.f / 64.f) + 1e-5f);
            if (ok) {
                int p = g_pos[e];
                float* dst = g_h + (size_t)p * 64 + seg * 16;
                int b = seg * 16;
#pragma unroll
                for (int j = 0; j < 16; j += 4) {
                    float4 o = make_float4(
                        d[j + 0] * rs * LNg[b + j + 0] + LNb[b + j + 0],
                        d[j + 1] * rs * LNg[b + j + 1] + LNb[b + j + 1],
                        d[j + 2] * rs * LNg[b + j + 2] + LNb[b + j + 2],
                        d[j + 3] * rs * LNg[b + j + 3] + LNb[b + j + 3]);
                    *(float4*)(dst + j) = o;
                }
            }
        }
        __syncthreads();
    }
}

// ---------------------------------------------------------------------------
// Node kernel: M-tile=64, 512 threads, 16 warps (4x4). g_agg holds the mean.
// ---------------------------------------------------------------------------
template <int KS, int NTW, bool TF32OUT>
__device__ __forceinline__ void mlp_layer64(const float* __restrict__ Ab,
                                            const float* __restrict__ W, int ldw,
                                            const float* __restrict__ BT, int ldbt,
                                            float* __restrict__ Ao,
                                            int rt, int nh) {
    wmma::fragment<wmma::accumulator, 16, 16, 8, float> acc[NTW];
#pragma unroll
    for (int nt = 0; nt < NTW; nt++)
        wmma::load_matrix_sync(acc[nt], BT + (nh * NTW + nt) * 16, ldbt,
                               wmma::mem_row_major);
#pragma unroll 2
    for (int ks = 0; ks < KS; ks++) {
        wmma::fragment<wmma::matrix_a, 16, 16, 8, wmma::precision::tf32,
                       wmma::row_major> af;
        wmma::load_matrix_sync(af, Ab + rt * 16 * LDA + ks * 8, LDA);
#pragma unroll
        for (int nt = 0; nt < NTW; nt++) {
            wmma::fragment<wmma::matrix_b, 16, 16, 8, wmma::precision::tf32,
                           wmma::row_major> bf;
            wmma::load_matrix_sync(bf, W + ks * 8 * ldw + (nh * NTW + nt) * 16, ldw);
            wmma::mma_sync(acc[nt], af, bf, acc[nt]);
        }
    }
    __syncthreads();
#pragma unroll
    for (int nt = 0; nt < NTW; nt++) {
#pragma unroll
        for (int i = 0; i < acc[nt].num_elements; i++) {
            float v = lrelu(acc[nt].x[i]);
            acc[nt].x[i] = TF32OUT ? to_tf32(v) : v;
        }
        wmma::store_matrix_sync(Ao + rt * 16 * LDA + (nh * NTW + nt) * 16,
                                acc[nt], LDA, wmma::mem_row_major);
    }
    __syncthreads();
}

#define M_A 0
#define M_W0 34816
#define M_W1 104448
#define M_W2 174080
#define M_BT0 210944
#define M_BT1 219136
#define M_BT2 227328
#define M_LN 231424
#define M_SM 231936

__global__ __launch_bounds__(512, 1)
void node_tc(const float* __restrict__ x,
             const float* __restrict__ w0g, const float* __restrict__ b0g,
             const float* __restrict__ w1g, const float* __restrict__ b1g,
             const float* __restrict__ w2g, const float* __restrict__ b2g,
             const float* __restrict__ gg, const float* __restrict__ btg,
             float* __restrict__ out, int N) {
    extern __shared__ char sm[];
    float* A = (float*)(sm + M_A);
    float* W0 = (float*)(sm + M_W0);
    float* W1 = (float*)(sm + M_W1);
    float* W2 = (float*)(sm + M_W2);
    float* BT0 = (float*)(sm + M_BT0);
    float* BT1 = (float*)(sm + M_BT1);
    float* BT2 = (float*)(sm + M_BT2);
    float* LN = (float*)(sm + M_LN);

    int tid = threadIdx.x;
    for (int i = tid; i < 128 * 128; i += 512) {
        int k = i >> 7, n = i & 127;
        W0[k * LDA + n] = to_tf32(w0g[i]);
        W1[k * LDA + n] = to_tf32(w1g[i]);
    }
    for (int i = tid; i < 128 * 64; i += 512) {
        int k = i >> 6, n = i & 63;
        W2[k * 72 + n] = to_tf32(w2g[i]);
    }
    for (int i = tid; i < 16 * 128; i += 512) {
        int n = i & 127;
        BT0[i] = b0g[n];
        BT1[i] = b1g[n];
    }
    for (int i = tid; i < 16 * 64; i += 512) BT2[i] = b2g[i & 63];
    if (tid < 64) { LN[tid] = gg[tid]; LN[64 + tid] = btg[tid]; }
    __syncthreads();

    int warp = tid >> 5;
    int rt = warp & 3, nh = warp >> 2;
    int r = tid >> 3, seg = tid & 7;
    int ntiles = (N + 63) >> 6;

    for (int gi = blockIdx.x; gi < ntiles; gi += gridDim.x) {
        int n = (gi << 6) + r;
        bool ok = n < N;
        {
            const float4* xp = (const float4*)(x + (size_t)n * 64);
            const float4* ap = (const float4*)(g_agg + (size_t)n * 64);
#pragma unroll
            for (int j = 0; j < 4; j++) {
                int q = seg * 4 + j;
                float4 v = ok ? (q < 16 ? __ldg(xp + q) : ap[q - 16])
                              : make_float4(0.f, 0.f, 0.f, 0.f);
                float4 o = make_float4(to_tf32(v.x), to_tf32(v.y),
                                       to_tf32(v.z), to_tf32(v.w));
                *(float4*)(A + r * LDA + q * 4) = o;
            }
        }
        __syncthreads();
        mlp_layer64<16, 2, true>(A, W0, LDA, BT0, 128, A, rt, nh);
        mlp_layer64<16, 2, true>(A, W1, LDA, BT1, 128, A, rt, nh);
        mlp_layer64<16, 1, false>(A, W2, 72, BT2, 64, A, rt, nh);
        {
            float4 v0 = *(float4*)(A + r * LDA + seg * 8);
            float4 v1 = *(float4*)(A + r * LDA + seg * 8 + 4);
            float s = v0.x + v0.y + v0.z + v0.w + v1.x + v1.y + v1.z + v1.w;
#pragma unroll
            for (int off = 4; off; off >>= 1) s += __shfl_xor_sync(0xffffffffu, s, off);
            float mu = s * (1.f / 64.f);
            float d[8] = {v0.x - mu, v0.y - mu, v0.z - mu, v0.w - mu,
                          v1.x - mu, v1.y - mu, v1.z - mu, v1.w - mu};
            float q = 0.f;
#pragma unroll
            for (int j = 0; j < 8; j++) q += d[j] * d[j];
#pragma unroll
            for (int off = 4; off; off >>= 1) q += __shfl_xor_sync(0xffffffffu, q, off);
            float rs = rsqrtf(q * (1.f / 64.f) + 1e-5f);
            if (ok) {
                int b = seg * 8;
                float4 o0 = make_float4(d[0] * rs * LN[b + 0] + LN[64 + b + 0],
                                        d[1] * rs * LN[b + 1] + LN[64 + b + 1],
                                        d[2] * rs * LN[b + 2] + LN[64 + b + 2],
                                        d[3] * rs * LN[b + 3] + LN[64 + b + 3]);
                float4 o1 = make_float4(d[4] * rs * LN[b + 4] + LN[64 + b + 4],
                                        d[5] * rs * LN[b + 5] + LN[64 + b + 5],
                                        d[6] * rs * LN[b + 6] + LN[64 + b + 6],
                                        d[7] * rs * LN[b + 7] + LN[64 + b + 7]);
                float4* op = (float4*)(out + (size_t)n * 64 + b);
                op[0] = o0;
                op[1] = o1;
            }
        }
        __syncthreads();
    }
}

// ---------------------------------------------------------------------------
extern "C" void kernel_launch(void* const* d_in, const int* in_sizes, int n_in,
                              void* d_out, int out_size) {
    const float* x = (const float*)d_in[0];
    const void* ei = (const void*)d_in[1];
    const float* ea = (const float*)d_in[2];
    const float* m1w0 = (const float*)d_in[5];
    const float* m1b0 = (const float*)d_in[6];
    const float* m1w1 = (const float*)d_in[7];
    const float* m1b1 = (const float*)d_in[8];
    const float* m1w2 = (const float*)d_in[9];
    const float* m1b2 = (const float*)d_in[10];
    const float* ln1g = (const float*)d_in[11];
    const float* ln1b = (const float*)d_in[12];
    const float* m2w0 = (const float*)d_in[13];
    const float* m2b0 = (const float*)d_in[14];
    const float* m2w1 = (const float*)d_in[15];
    const float* m2b1 = (const float*)d_in[16];
    const float* m2w2 = (const float*)d_in[17];
    const float* m2b2 = (const float*)d_in[18];
    const float* ln2g = (const float*)d_in[19];
    const float* ln2b = (const float*)d_in[20];

    int N = in_sizes[0] / 64;
    int E = in_sizes[1] / 2;
    if (N > N_MAX) N = N_MAX;
    if (E > E_MAX) E = E_MAX;
    float* out = (float*)d_out;

    int dev = 0;
    cudaGetDevice(&dev);
    int nsm = 148;
    cudaDeviceGetAttribute(&nsm, cudaDevAttrMultiProcessorCount, dev);

    zero_kernel<<<256, 256>>>(N);
    detect_kernel<<<512, 256>>>((const long long*)ei, E, N);
    convert_kernel<<<512, 256>>>(ei, E, N);
    scan_kernel<<<1, 1024>>>(N);
    fill_kernel<<<512, 256>>>(E);

    cudaFuncSetAttribute(edge_tc, cudaFuncAttributeMaxDynamicSharedMemorySize, E_SM);
    cudaFuncSetAttribute(node_tc, cudaFuncAttributeMaxDynamicSharedMemorySize, M_SM);

    edge_tc<<<nsm, 512, E_SM>>>(x, ea, m1w0, m1b0, m1w1, m1b1, m1w2, m1b2,
                                ln1g, ln1b, E);
    agg_kernel<<<2 * nsm, 512>>>(N);
    node_tc<<<nsm, 512, M_SM>>>(x, m2w0, m2b0, m2w1, m2b1, m2w2, m2b2,
                                ln2g, ln2b, out, N);
}

// round 15
// speedup vs baseline: 3.7572x; 3.7572x over previous
#include <cuda_runtime.h>
#include <cuda_fp16.h>
#include <mma.h>

using namespace nvcuda;

#define N_MAX 50000
#define E_MAX 800000

// Scratch (allocation-free rule: __device__ globals)
__device__ float g_agg[N_MAX * 64];
__device__ float g_cnt[N_MAX];
__device__ int g_row[E_MAX];
__device__ int g_col[E_MAX];
__device__ int g_is32;

// ---------------------------------------------------------------------------
__device__ __forceinline__ float lrelu(float v) { return v > 0.f ? v : 0.01f * v; }

__device__ __forceinline__ void red_add_v4(float* p, float a, float b, float c, float d) {
    asm volatile("red.global.add.v4.f32 [%0], {%1, %2, %3, %4};"
                 :: "l"(p), "f"(a), "f"(b), "f"(c), "f"(d) : "memory");
}

__device__ __forceinline__ unsigned h2u(half2 h) {
    return *(unsigned*)&h;
}

// ---------------------------------------------------------------------------
// Prep kernels (R13-proven)
// ---------------------------------------------------------------------------
__global__ void zero_kernel(int N) {
    int i = blockIdx.x * blockDim.x + threadIdx.x;
    int stride = gridDim.x * blockDim.x;
    if (i == 0) g_is32 = 0;
    int n4 = N * 16;
    float4 z = make_float4(0.f, 0.f, 0.f, 0.f);
    for (int j = i; j < n4; j += stride) ((float4*)g_agg)[j] = z;
    for (int j = i; j < N; j += stride) g_cnt[j] = 0.f;
}

__global__ void detect_kernel(const long long* __restrict__ ei64, int E, int N) {
    int i = blockIdx.x * blockDim.x + threadIdx.x;
    int stride = gridDim.x * blockDim.x;
    int bad = 0;
    for (int j = i; j < E; j += stride) {
        long long v = ei64[j];
        if (v < 0 || v >= (long long)N) bad = 1;
    }
    if (__ballot_sync(0xffffffffu, bad) && (threadIdx.x & 31) == 0)
        atomicOr(&g_is32, 1);
}

__global__ void convert_kernel(const void* __restrict__ eiraw, int E, int N) {
    int i = blockIdx.x * blockDim.x + threadIdx.x;
    int stride = gridDim.x * blockDim.x;
    int is32 = g_is32;
    if (is32) {
        const int* p = (const int*)eiraw;
        for (int j = i; j < E; j += stride) {
            g_row[j] = min(max(p[j], 0), N - 1);
            g_col[j] = min(max(p[E + j], 0), N - 1);
        }
    } else {
        const long long* p = (const long long*)eiraw;
        for (int j = i; j < E; j += stride) {
            g_row[j] = min(max((int)p[j], 0), N - 1);
            g_col[j] = min(max((int)p[E + j], 0), N - 1);
        }
    }
}

// ---------------------------------------------------------------------------
#define LDAH 136  // half elements per row (272 B)
#define LDF 136   // float elements per row

// One fp16 MLP layer. Warp (rt, nh): rows rt*(MT*16)+mt*16, cols (nh*NT+nt)*16.
// Reads half A (ld LDAH), writes activated fp32 result to F (ld LDF).
// Caller must __syncthreads() after (and convert F->Ah if another layer follows).
template <int MT, int NT, int KS>
__device__ __forceinline__ void mlp_half(const __half* __restrict__ Ah,
                                         const __half* __restrict__ W, int ldw,
                                         const float* __restrict__ biasRow,
                                         float* __restrict__ F,
                                         int rt, int nh) {
    wmma::fragment<wmma::accumulator, 16, 16, 16, float> acc[MT][NT];
#pragma unroll
    for (int mt = 0; mt < MT; mt++)
#pragma unroll
        for (int nt = 0; nt < NT; nt++)
            wmma::load_matrix_sync(acc[mt][nt], biasRow + (nh * NT + nt) * 16, 0,
                                   wmma::mem_row_major);
#pragma unroll
    for (int ks = 0; ks < KS; ks++) {
        wmma::fragment<wmma::matrix_a, 16, 16, 16, __half, wmma::row_major> af[MT];
#pragma unroll
        for (int mt = 0; mt < MT; mt++)
            wmma::load_matrix_sync(af[mt],
                                   Ah + (rt * (MT * 16) + mt * 16) * LDAH + ks * 16,
                                   LDAH);
        wmma::fragment<wmma::matrix_b, 16, 16, 16, __half, wmma::row_major> bf[NT];
#pragma unroll
        for (int nt = 0; nt < NT; nt++)
            wmma::load_matrix_sync(bf[nt], W + ks * 16 * ldw + (nh * NT + nt) * 16, ldw);
#pragma unroll
        for (int mt = 0; mt < MT; mt++)
#pragma unroll
            for (int nt = 0; nt < NT; nt++)
                wmma::mma_sync(acc[mt][nt], af[mt], bf[nt], acc[mt][nt]);
    }
#pragma unroll
    for (int mt = 0; mt < MT; mt++)
#pragma unroll
        for (int nt = 0; nt < NT; nt++) {
#pragma unroll
            for (int i = 0; i < acc[mt][nt].num_elements; i++)
                acc[mt][nt].x[i] = lrelu(acc[mt][nt].x[i]);
            wmma::store_matrix_sync(F + (rt * (MT * 16) + mt * 16) * LDF +
                                        (nh * NT + nt) * 16,
                                    acc[mt][nt], LDF, wmma::mem_row_major);
        }
}

// Linear fp32 -> fp16 conversion of a whole padded activation block.
__device__ __forceinline__ void conv_f2h(const float* __restrict__ F,
                                         __half* __restrict__ Ah, int total,
                                         int tid, int nthr) {
    for (int i = tid * 4; i < total; i += nthr * 4) {
        float4 v = *(const float4*)(F + i);
        half2 a = __floats2half2_rn(v.x, v.y);
        half2 b = __floats2half2_rn(v.z, v.w);
        *(uint2*)(Ah + i) = make_uint2(h2u(a), h2u(b));
    }
}

// ---------------------------------------------------------------------------
// Edge kernel: M-tile=128, 512 threads = 16 warps (4 rt x 4 nh), fp16 MMA.
// SMEM: Ah[128][136]h | F[128][136]f | W0h[96][136]h | W1h[128][136]h |
//       W2h[128][72]h | biases f32
#define E_AH 0
#define E_F  34816
#define E_W0 104448
#define E_W1 130560
#define E_W2 165376
#define E_BS 183808
#define E_SM 185600

__global__ __launch_bounds__(512, 1)
void edge_tc(const float* __restrict__ x, const float* __restrict__ ea,
             const float* __restrict__ w0g, const float* __restrict__ b0g,
             const float* __restrict__ w1g, const float* __restrict__ b1g,
             const float* __restrict__ w2g, const float* __restrict__ b2g,
             const float* __restrict__ gg, const float* __restrict__ btg, int E) {
    extern __shared__ char sm[];
    __half* Ah = (__half*)(sm + E_AH);
    float* F = (float*)(sm + E_F);
    __half* W0 = (__half*)(sm + E_W0);
    __half* W1 = (__half*)(sm + E_W1);
    __half* W2 = (__half*)(sm + E_W2);
    float* BS = (float*)(sm + E_BS);
    float* B0 = BS, *B1 = BS + 128, *B2 = BS + 256, *LNg = BS + 320, *LNb = BS + 384;

    int tid = threadIdx.x;
    for (int i = tid; i < 96 * 128; i += 512) {
        int k = i >> 7, n = i & 127;
        W0[k * LDAH + n] = __float2half(w0g[i]);
    }
    for (int i = tid; i < 128 * 128; i += 512) {
        int k = i >> 7, n = i & 127;
        W1[k * LDAH + n] = __float2half(w1g[i]);
    }
    for (int i = tid; i < 128 * 64; i += 512) {
        int k = i >> 6, n = i & 63;
        W2[k * 72 + n] = __float2half(w2g[i]);
    }
    if (tid < 128) { B0[tid] = b0g[tid]; B1[tid] = b1g[tid]; }
    if (tid < 64) { B2[tid] = b2g[tid]; LNg[tid] = gg[tid]; LNb[tid] = btg[tid]; }
    __syncthreads();

    int warp = tid >> 5;
    int rt = warp & 3, nh = warp >> 2;
    int r = tid >> 2, seg = tid & 3;  // gather/LN role: 4 threads per row
    int ntiles = (E + 127) >> 7;

    for (int gi = blockIdx.x; gi < ntiles; gi += gridDim.x) {
        int e = (gi << 7) + r;
        bool ok = e < E;
        // ---- Gather: row r, 96 cols (x[row] 64 ++ ea 32) -> half, 3 chunks of 8
        {
            int rw = ok ? g_row[e] : 0;
            const float4* xp = (const float4*)(x + (size_t)rw * 64);
            const float4* ep = (const float4*)(ea + (size_t)e * 32);
#pragma unroll
            for (int j = 0; j < 3; j++) {
                int c = seg * 3 + j;  // 8-col chunk index, 0..11
                float4 v0, v1;
                if (ok) {
                    if (c < 8) { v0 = __ldg(xp + c * 2); v1 = __ldg(xp + c * 2 + 1); }
                    else { v0 = __ldg(ep + (c - 8) * 2); v1 = __ldg(ep + (c - 8) * 2 + 1); }
                } else {
                    v0 = v1 = make_float4(0.f, 0.f, 0.f, 0.f);
                }
                half2 h0 = __floats2half2_rn(v0.x, v0.y);
                half2 h1 = __floats2half2_rn(v0.z, v0.w);
                half2 h2 = __floats2half2_rn(v1.x, v1.y);
                half2 h3 = __floats2half2_rn(v1.z, v1.w);
                *(uint4*)(Ah + r * LDAH + c * 8) =
                    make_uint4(h2u(h0), h2u(h1), h2u(h2), h2u(h3));
            }
        }
        __syncthreads();
        // ---- Layer 0 (K=96): MMA -> F, convert F -> Ah
        mlp_half<2, 2, 6>(Ah, W0, LDAH, B0, F, rt, nh);
        __syncthreads();
        conv_f2h(F, Ah, 128 * LDF, tid, 512);
        __syncthreads();
        // ---- Layer 1 (K=128)
        mlp_half<2, 2, 8>(Ah, W1, LDAH, B1, F, rt, nh);
        __syncthreads();
        conv_f2h(F, Ah, 128 * LDF, tid, 512);
        __syncthreads();
        // ---- Layer 2 (K=128, N=64): result stays in F (fp32)
        mlp_half<2, 1, 8>(Ah, W2, 72, B2, F, rt, nh);
        __syncthreads();
        // ---- LayerNorm per row + atomic scatter (F holds 128x64 post-lrelu)
        {
            float4 v0 = *(float4*)(F + r * LDF + seg * 16);
            float4 v1 = *(float4*)(F + r * LDF + seg * 16 + 4);
            float4 v2 = *(float4*)(F + r * LDF + seg * 16 + 8);
            float4 v3 = *(float4*)(F + r * LDF + seg * 16 + 12);
            float s = v0.x + v0.y + v0.z + v0.w + v1.x + v1.y + v1.z + v1.w +
                      v2.x + v2.y + v2.z + v2.w + v3.x + v3.y + v3.z + v3.w;
#pragma unroll
            for (int off = 2; off; off >>= 1) s += __shfl_xor_sync(0xffffffffu, s, off);
            float mu = s * (1.f / 64.f);
            float d[16] = {v0.x - mu, v0.y - mu, v0.z - mu, v0.w - mu,
                           v1.x - mu, v1.y - mu, v1.z - mu, v1.w - mu,
                           v2.x - mu, v2.y - mu, v2.z - mu, v2.w - mu,
                           v3.x - mu, v3.y - mu, v3.z - mu, v3.w - mu};
            float q = 0.f;
#pragma unroll
            for (int j = 0; j < 16; j++) q += d[j] * d[j];
#pragma unroll
            for (int off = 2; off; off >>= 1) q += __shfl_xor_sync(0xffffffffu, q, off);
            float rs = rsqrtf(q * (1.f / 64.f) + 1e-5f);
            if (ok) {
                int c = g_col[e];
                float* dst = g_agg + (size_t)c * 64 + seg * 16;
                int b = seg * 16;
#pragma unroll
                for (int j = 0; j < 16; j += 4)
                    red_add_v4(dst + j,
                               d[j + 0] * rs * LNg[b + j + 0] + LNb[b + j + 0],
                               d[j + 1] * rs * LNg[b + j + 1] + LNb[b + j + 1],
                               d[j + 2] * rs * LNg[b + j + 2] + LNb[b + j + 2],
                               d[j + 3] * rs * LNg[b + j + 3] + LNb[b + j + 3]);
                if (seg == 0) atomicAdd(g_cnt + c, 1.f);
            }
        }
        __syncthreads();
    }
}

// ---------------------------------------------------------------------------
// Node kernel: M-tile=64, 512 threads = 16 warps (4 rt x 4 nh), fp16 MMA.
// SMEM: Ah[64][136]h | F[64][136]f | W0h[128][136]h | W1h | W2h[128][72]h | biases
#define M_AH 0
#define M_F  17408
#define M_W0 52224
#define M_W1 87040
#define M_W2 121856
#define M_BS 140288
#define M_SM 142080

__global__ __launch_bounds__(512, 1)
void node_tc(const float* __restrict__ x,
             const float* __restrict__ w0g, const float* __restrict__ b0g,
             const float* __restrict__ w1g, const float* __restrict__ b1g,
             const float* __restrict__ w2g, const float* __restrict__ b2g,
             const float* __restrict__ gg, const float* __restrict__ btg,
             float* __restrict__ out, int N) {
    extern __shared__ char sm[];
    __half* Ah = (__half*)(sm + M_AH);
    float* F = (float*)(sm + M_F);
    __half* W0 = (__half*)(sm + M_W0);
    __half* W1 = (__half*)(sm + M_W1);
    __half* W2 = (__half*)(sm + M_W2);
    float* BS = (float*)(sm + M_BS);
    float* B0 = BS, *B1 = BS + 128, *B2 = BS + 256, *LNg = BS + 320, *LNb = BS + 384;

    int tid = threadIdx.x;
    for (int i = tid; i < 128 * 128; i += 512) {
        int k = i >> 7, n = i & 127;
        W0[k * LDAH + n] = __float2half(w0g[i]);
        W1[k * LDAH + n] = __float2half(w1g[i]);
    }
    for (int i = tid; i < 128 * 64; i += 512) {
        int k = i >> 6, n = i & 63;
        W2[k * 72 + n] = __float2half(w2g[i]);
    }
    if (tid < 128) { B0[tid] = b0g[tid]; B1[tid] = b1g[tid]; }
    if (tid < 64) { B2[tid] = b2g[tid]; LNg[tid] = gg[tid]; LNb[tid] = btg[tid]; }
    __syncthreads();

    int warp = tid >> 5;
    int rt = warp & 3, nh = warp >> 2;
    int r = tid >> 3, seg = tid & 7;  // gather/LN role: 8 threads per row
    int ntiles = (N + 63) >> 6;

    for (int gi = blockIdx.x; gi < ntiles; gi += gridDim.x) {
        int n = (gi << 6) + r;
        bool ok = n < N;
        // ---- Gather: 128 cols (x 64 ++ agg/max(cnt,1) 64) -> half, 2 chunks of 8
        {
            float inv = ok ? 1.f / fmaxf(g_cnt[n], 1.f) : 0.f;
            const float4* xp = (const float4*)(x + (size_t)n * 64);
            const float4* ap = (const float4*)(g_agg + (size_t)n * 64);
#pragma unroll
            for (int j = 0; j < 2; j++) {
                int c = seg * 2 + j;  // 8-col chunk, 0..15
                float4 v0, v1;
                if (ok) {
                    if (c < 8) { v0 = __ldg(xp + c * 2); v1 = __ldg(xp + c * 2 + 1); }
                    else {
                        v0 = ap[(c - 8) * 2];
                        v1 = ap[(c - 8) * 2 + 1];
                        v0.x *= inv; v0.y *= inv; v0.z *= inv; v0.w *= inv;
                        v1.x *= inv; v1.y *= inv; v1.z *= inv; v1.w *= inv;
                    }
                } else {
                    v0 = v1 = make_float4(0.f, 0.f, 0.f, 0.f);
                }
                half2 h0 = __floats2half2_rn(v0.x, v0.y);
                half2 h1 = __floats2half2_rn(v0.z, v0.w);
                half2 h2 = __floats2half2_rn(v1.x, v1.y);
                half2 h3 = __floats2half2_rn(v1.z, v1.w);
                *(uint4*)(Ah + r * LDAH + c * 8) =
                    make_uint4(h2u(h0), h2u(h1), h2u(h2), h2u(h3));
            }
        }
        __syncthreads();
        mlp_half<1, 2, 8>(Ah, W0, LDAH, B0, F, rt, nh);
        __syncthreads();
        conv_f2h(F, Ah, 64 * LDF, tid, 512);
        __syncthreads();
        mlp_half<1, 2, 8>(Ah, W1, LDAH, B1, F, rt, nh);
        __syncthreads();
        conv_f2h(F, Ah, 64 * LDF, tid, 512);
        __syncthreads();
        mlp_half<1, 1, 8>(Ah, W2, 72, B2, F, rt, nh);
        __syncthreads();
        // ---- LayerNorm per row + store (F holds 64x64 post-lrelu)
        {
            float4 v0 = *(float4*)(F + r * LDF + seg * 8);
            float4 v1 = *(float4*)(F + r * LDF + seg * 8 + 4);
            float s = v0.x + v0.y + v0.z + v0.w + v1.x + v1.y + v1.z + v1.w;
#pragma unroll
            for (int off = 4; off; off >>= 1) s += __shfl_xor_sync(0xffffffffu, s, off);
            float mu = s * (1.f / 64.f);
            float d[8] = {v0.x - mu, v0.y - mu, v0.z - mu, v0.w - mu,
                          v1.x - mu, v1.y - mu, v1.z - mu, v1.w - mu};
            float q = 0.f;
#pragma unroll
            for (int j = 0; j < 8; j++) q += d[j] * d[j];
#pragma unroll
            for (int off = 4; off; off >>= 1) q += __shfl_xor_sync(0xffffffffu, q, off);
            float rs = rsqrtf(q * (1.f / 64.f) + 1e-5f);
            if (ok) {
                int b = seg * 8;
                float4 o0 = make_float4(d[0] * rs * LNg[b + 0] + LNb[b + 0],
                                        d[1] * rs * LNg[b + 1] + LNb[b + 1],
                                        d[2] * rs * LNg[b + 2] + LNb[b + 2],
                                        d[3] * rs * LNg[b + 3] + LNb[b + 3]);
                float4 o1 = make_float4(d[4] * rs * LNg[b + 4] + LNb[b + 4],
                                        d[5] * rs * LNg[b + 5] + LNb[b + 5],
                                        d[6] * rs * LNg[b + 6] + LNb[b + 6],
                                        d[7] * rs * LNg[b + 7] + LNb[b + 7]);
                float4* op = (float4*)(out + (size_t)n * 64 + b);
                op[0] = o0;
                op[1] = o1;
            }
        }
        __syncthreads();
    }
}

// ---------------------------------------------------------------------------
extern "C" void kernel_launch(void* const* d_in, const int* in_sizes, int n_in,
                              void* d_out, int out_size) {
    const float* x = (const float*)d_in[0];
    const void* ei = (const void*)d_in[1];
    const float* ea = (const float*)d_in[2];
    const float* m1w0 = (const float*)d_in[5];
    const float* m1b0 = (const float*)d_in[6];
    const float* m1w1 = (const float*)d_in[7];
    const float* m1b1 = (const float*)d_in[8];
    const float* m1w2 = (const float*)d_in[9];
    const float* m1b2 = (const float*)d_in[10];
    const float* ln1g = (const float*)d_in[11];
    const float* ln1b = (const float*)d_in[12];
    const float* m2w0 = (const float*)d_in[13];
    const float* m2b0 = (const float*)d_in[14];
    const float* m2w1 = (const float*)d_in[15];
    const float* m2b1 = (const float*)d_in[16];
    const float* m2w2 = (const float*)d_in[17];
    const float* m2b2 = (const float*)d_in[18];
    const float* ln2g = (const float*)d_in[19];
    const float* ln2b = (const float*)d_in[20];

    int N = in_sizes[0] / 64;
    int E = in_sizes[1] / 2;
    if (N > N_MAX) N = N_MAX;
    if (E > E_MAX) E = E_MAX;
    float* out = (float*)d_out;

    int dev = 0;
    cudaGetDevice(&dev);
    int nsm = 148;
    cudaDeviceGetAttribute(&nsm, cudaDevAttrMultiProcessorCount, dev);

    zero_kernel<<<256, 256>>>(N);
    detect_kernel<<<512, 256>>>((const long long*)ei, E, N);
    convert_kernel<<<512, 256>>>(ei, E, N);

    cudaFuncSetAttribute(edge_tc, cudaFuncAttributeMaxDynamicSharedMemorySize, E_SM);
    cudaFuncSetAttribute(node_tc, cudaFuncAttributeMaxDynamicSharedMemorySize, M_SM);

    edge_tc<<<nsm, 512, E_SM>>>(x, ea, m1w0, m1b0, m1w1, m1b1, m1w2, m1b2,
                                ln1g, ln1b, E);
    node_tc<<<nsm, 512, M_SM>>>(x, m2w0, m2b0, m2w1, m2b1, m2w2, m2b2,
                                ln2g, ln2b, out, N);
}

// round 16
// speedup vs baseline: 4.0806x; 1.0861x over previous
#include <cuda_runtime.h>
#include <cuda_fp16.h>
#include <mma.h>

using namespace nvcuda;

#define N_MAX 50000
#define E_MAX 800000

// Scratch (allocation-free rule: __device__ globals)
__device__ float g_agg[N_MAX * 64];
__device__ float g_cnt[N_MAX];
__device__ int g_row[E_MAX];
__device__ int g_col[E_MAX];
__device__ int g_is32;

// ---------------------------------------------------------------------------
__device__ __forceinline__ float lrelu(float v) { return v > 0.f ? v : 0.01f * v; }

__device__ __forceinline__ void red_add_v4(float* p, float a, float b, float c, float d) {
    asm volatile("red.global.add.v4.f32 [%0], {%1, %2, %3, %4};"
                 :: "l"(p), "f"(a), "f"(b), "f"(c), "f"(d) : "memory");
}

__device__ __forceinline__ unsigned h2u(half2 h) {
    return *(unsigned*)&h;
}

// ---------------------------------------------------------------------------
// Prep kernels (proven)
// ---------------------------------------------------------------------------
__global__ void zero_kernel(int N) {
    int i = blockIdx.x * blockDim.x + threadIdx.x;
    int stride = gridDim.x * blockDim.x;
    if (i == 0) g_is32 = 0;
    int n4 = N * 16;
    float4 z = make_float4(0.f, 0.f, 0.f, 0.f);
    for (int j = i; j < n4; j += stride) ((float4*)g_agg)[j] = z;
    for (int j = i; j < N; j += stride) g_cnt[j] = 0.f;
}

__global__ void detect_kernel(const long long* __restrict__ ei64, int E, int N) {
    int i = blockIdx.x * blockDim.x + threadIdx.x;
    int stride = gridDim.x * blockDim.x;
    int bad = 0;
    for (int j = i; j < E; j += stride) {
        long long v = ei64[j];
        if (v < 0 || v >= (long long)N) bad = 1;
    }
    if (__ballot_sync(0xffffffffu, bad) && (threadIdx.x & 31) == 0)
        atomicOr(&g_is32, 1);
}

__global__ void convert_kernel(const void* __restrict__ eiraw, int E, int N) {
    int i = blockIdx.x * blockDim.x + threadIdx.x;
    int stride = gridDim.x * blockDim.x;
    int is32 = g_is32;
    if (is32) {
        const int* p = (const int*)eiraw;
        for (int j = i; j < E; j += stride) {
            g_row[j] = min(max(p[j], 0), N - 1);
            g_col[j] = min(max(p[E + j], 0), N - 1);
        }
    } else {
        const long long* p = (const long long*)eiraw;
        for (int j = i; j < E; j += stride) {
            g_row[j] = min(max((int)p[j], 0), N - 1);
            g_col[j] = min(max((int)p[E + j], 0), N - 1);
        }
    }
}

// ---------------------------------------------------------------------------
#define LDAH 136  // half elements per row (272 B): +4 banks/row, conflict-free
#define LDF2 76   // float elements per row (304 B): +12 banks/row, conflict-free

// One fp16 MLP layer. Warp (rt, nh): rows rt*(MT*16)+mt*16, cols (nh*NT+nt)*16.
// fp32 accumulate; activated output stored EITHER directly as half into Hout
// (ping-pong buffer, ld LDAH) using the shared f32/f16 accumulator fragment
// element order, OR as fp32 into Fout (ld LDF2) for the final layer.
template <int MT, int NT, int KS, bool HALF_OUT>
__device__ __forceinline__ void mlp_half(const __half* __restrict__ Ah,
                                         const __half* __restrict__ W, int ldw,
                                         const float* __restrict__ biasRow,
                                         __half* __restrict__ Hout,
                                         float* __restrict__ Fout,
                                         int rt, int nh) {
    wmma::fragment<wmma::accumulator, 16, 16, 16, float> acc[MT][NT];
#pragma unroll
    for (int mt = 0; mt < MT; mt++)
#pragma unroll
        for (int nt = 0; nt < NT; nt++)
            wmma::load_matrix_sync(acc[mt][nt], biasRow + (nh * NT + nt) * 16, 0,
                                   wmma::mem_row_major);
#pragma unroll
    for (int ks = 0; ks < KS; ks++) {
        wmma::fragment<wmma::matrix_a, 16, 16, 16, __half, wmma::row_major> af[MT];
#pragma unroll
        for (int mt = 0; mt < MT; mt++)
            wmma::load_matrix_sync(af[mt],
                                   Ah + (rt * (MT * 16) + mt * 16) * LDAH + ks * 16,
                                   LDAH);
        wmma::fragment<wmma::matrix_b, 16, 16, 16, __half, wmma::row_major> bf[NT];
#pragma unroll
        for (int nt = 0; nt < NT; nt++)
            wmma::load_matrix_sync(bf[nt], W + ks * 16 * ldw + (nh * NT + nt) * 16, ldw);
#pragma unroll
        for (int mt = 0; mt < MT; mt++)
#pragma unroll
            for (int nt = 0; nt < NT; nt++)
                wmma::mma_sync(acc[mt][nt], af[mt], bf[nt], acc[mt][nt]);
    }
#pragma unroll
    for (int mt = 0; mt < MT; mt++)
#pragma unroll
        for (int nt = 0; nt < NT; nt++) {
            int ro = rt * (MT * 16) + mt * 16, co = (nh * NT + nt) * 16;
            if (HALF_OUT) {
                wmma::fragment<wmma::accumulator, 16, 16, 16, __half> hc;
#pragma unroll
                for (int i = 0; i < acc[mt][nt].num_elements; i++)
                    hc.x[i] = __float2half(lrelu(acc[mt][nt].x[i]));
                wmma::store_matrix_sync(Hout + ro * LDAH + co, hc, LDAH,
                                        wmma::mem_row_major);
            } else {
#pragma unroll
                for (int i = 0; i < acc[mt][nt].num_elements; i++)
                    acc[mt][nt].x[i] = lrelu(acc[mt][nt].x[i]);
                wmma::store_matrix_sync(Fout + ro * LDF2 + co, acc[mt][nt], LDF2,
                                        wmma::mem_row_major);
            }
        }
}

// ---------------------------------------------------------------------------
// Edge kernel: M-tile=128, 512 threads = 16 warps (4 rt x 4 nh), fp16 MMA,
// ping-pong half activations, direct half stores.
// SMEM bytes: Ah0 34816 | Ah1 34816 | F 38912 | W0 26112 | W1 34816 |
//             W2 18432 | BS 1792  => total 189696
#define E_A0 0
#define E_A1 34816
#define E_F  69632
#define E_W0 108544
#define E_W1 134656
#define E_W2 169472
#define E_BS 187904
#define E_SM 189696

__global__ __launch_bounds__(512, 1)
void edge_tc(const float* __restrict__ x, const float* __restrict__ ea,
             const float* __restrict__ w0g, const float* __restrict__ b0g,
             const float* __restrict__ w1g, const float* __restrict__ b1g,
             const float* __restrict__ w2g, const float* __restrict__ b2g,
             const float* __restrict__ gg, const float* __restrict__ btg, int E) {
    extern __shared__ char sm[];
    __half* Ah0 = (__half*)(sm + E_A0);
    __half* Ah1 = (__half*)(sm + E_A1);
    float* F = (float*)(sm + E_F);
    __half* W0 = (__half*)(sm + E_W0);
    __half* W1 = (__half*)(sm + E_W1);
    __half* W2 = (__half*)(sm + E_W2);
    float* BS = (float*)(sm + E_BS);
    float* B0 = BS, *B1 = BS + 128, *B2 = BS + 256, *LNg = BS + 320, *LNb = BS + 384;

    int tid = threadIdx.x;
    for (int i = tid; i < 96 * 128; i += 512) {
        int k = i >> 7, n = i & 127;
        W0[k * LDAH + n] = __float2half(w0g[i]);
    }
    for (int i = tid; i < 128 * 128; i += 512) {
        int k = i >> 7, n = i & 127;
        W1[k * LDAH + n] = __float2half(w1g[i]);
    }
    for (int i = tid; i < 128 * 64; i += 512) {
        int k = i >> 6, n = i & 63;
        W2[k * 72 + n] = __float2half(w2g[i]);
    }
    if (tid < 128) { B0[tid] = b0g[tid]; B1[tid] = b1g[tid]; }
    if (tid < 64) { B2[tid] = b2g[tid]; LNg[tid] = gg[tid]; LNb[tid] = btg[tid]; }
    __syncthreads();

    int warp = tid >> 5;
    int rt = warp & 3, nh = warp >> 2;
    int r = tid >> 2, seg = tid & 3;  // gather/LN role: 4 threads per row
    int ntiles = (E + 127) >> 7;

    for (int gi = blockIdx.x; gi < ntiles; gi += gridDim.x) {
        int e = (gi << 7) + r;
        bool ok = e < E;
        // ---- Gather: row r, 96 cols (x[row] 64 ++ ea 32) -> half, 3 chunks of 8
        {
            int rw = ok ? g_row[e] : 0;
            const float4* xp = (const float4*)(x + (size_t)rw * 64);
            const float4* ep = (const float4*)(ea + (size_t)e * 32);
#pragma unroll
            for (int j = 0; j < 3; j++) {
                int c = seg * 3 + j;  // 8-col chunk index, 0..11
                float4 v0, v1;
                if (ok) {
                    if (c < 8) { v0 = __ldg(xp + c * 2); v1 = __ldg(xp + c * 2 + 1); }
                    else { v0 = __ldg(ep + (c - 8) * 2); v1 = __ldg(ep + (c - 8) * 2 + 1); }
                } else {
                    v0 = v1 = make_float4(0.f, 0.f, 0.f, 0.f);
                }
                half2 h0 = __floats2half2_rn(v0.x, v0.y);
                half2 h1 = __floats2half2_rn(v0.z, v0.w);
                half2 h2 = __floats2half2_rn(v1.x, v1.y);
                half2 h3 = __floats2half2_rn(v1.z, v1.w);
                *(uint4*)(Ah0 + r * LDAH + c * 8) =
                    make_uint4(h2u(h0), h2u(h1), h2u(h2), h2u(h3));
            }
        }
        __syncthreads();
        // ---- Layer 0 (K=96): Ah0 -> Ah1 (half, direct)
        mlp_half<2, 2, 6, true>(Ah0, W0, LDAH, B0, Ah1, nullptr, rt, nh);
        __syncthreads();
        // ---- Layer 1 (K=128): Ah1 -> Ah0
        mlp_half<2, 2, 8, true>(Ah1, W1, LDAH, B1, Ah0, nullptr, rt, nh);
        __syncthreads();
        // ---- Layer 2 (K=128, N=64): Ah0 -> F (fp32)
        mlp_half<2, 1, 8, false>(Ah0, W2, 72, B2, nullptr, F, rt, nh);
        __syncthreads();
        // ---- LayerNorm per row + atomic scatter (F holds 128x64 post-lrelu)
        {
            float4 v0 = *(float4*)(F + r * LDF2 + seg * 16);
            float4 v1 = *(float4*)(F + r * LDF2 + seg * 16 + 4);
            float4 v2 = *(float4*)(F + r * LDF2 + seg * 16 + 8);
            float4 v3 = *(float4*)(F + r * LDF2 + seg * 16 + 12);
            float s = v0.x + v0.y + v0.z + v0.w + v1.x + v1.y + v1.z + v1.w +
                      v2.x + v2.y + v2.z + v2.w + v3.x + v3.y + v3.z + v3.w;
#pragma unroll
            for (int off = 2; off; off >>= 1) s += __shfl_xor_sync(0xffffffffu, s, off);
            float mu = s * (1.f / 64.f);
            float d[16] = {v0.x - mu, v0.y - mu, v0.z - mu, v0.w - mu,
                           v1.x - mu, v1.y - mu, v1.z - mu, v1.w - mu,
                           v2.x - mu, v2.y - mu, v2.z - mu, v2.w - mu,
                           v3.x - mu, v3.y - mu, v3.z - mu, v3.w - mu};
            float q = 0.f;
#pragma unroll
            for (int j = 0; j < 16; j++) q += d[j] * d[j];
#pragma unroll
            for (int off = 2; off; off >>= 1) q += __shfl_xor_sync(0xffffffffu, q, off);
            float rs = rsqrtf(q * (1.f / 64.f) + 1e-5f);
            if (ok) {
                int c = g_col[e];
                float* dst = g_agg + (size_t)c * 64 + seg * 16;
                int b = seg * 16;
#pragma unroll
                for (int j = 0; j < 16; j += 4)
                    red_add_v4(dst + j,
                               d[j + 0] * rs * LNg[b + j + 0] + LNb[b + j + 0],
                               d[j + 1] * rs * LNg[b + j + 1] + LNb[b + j + 1],
                               d[j + 2] * rs * LNg[b + j + 2] + LNb[b + j + 2],
                               d[j + 3] * rs * LNg[b + j + 3] + LNb[b + j + 3]);
                if (seg == 0) atomicAdd(g_cnt + c, 1.f);
            }
        }
        // no trailing sync needed: next gather writes Ah0, whose last readers
        // (L2) are behind the post-L2 barrier; LN reads F, next written only
        // after 3 more barriers.
    }
}

// ---------------------------------------------------------------------------
// Node kernel: M-tile=64, 512 threads = 16 warps (4 rt x 4 nh), same scheme.
// SMEM bytes: Ah0 17408 | Ah1 17408 | F 19456 | W0 34816 | W1 34816 |
//             W2 18432 | BS 1792 => total 144128
#define M_A0 0
#define M_A1 17408
#define M_F  34816
#define M_W0 54272
#define M_W1 89088
#define M_W2 123904
#define M_BS 142336
#define M_SM 144128

__global__ __launch_bounds__(512, 1)
void node_tc(const float* __restrict__ x,
             const float* __restrict__ w0g, const float* __restrict__ b0g,
             const float* __restrict__ w1g, const float* __restrict__ b1g,
             const float* __restrict__ w2g, const float* __restrict__ b2g,
             const float* __restrict__ gg, const float* __restrict__ btg,
             float* __restrict__ out, int N) {
    extern __shared__ char sm[];
    __half* Ah0 = (__half*)(sm + M_A0);
    __half* Ah1 = (__half*)(sm + M_A1);
    float* F = (float*)(sm + M_F);
    __half* W0 = (__half*)(sm + M_W0);
    __half* W1 = (__half*)(sm + M_W1);
    __half* W2 = (__half*)(sm + M_W2);
    float* BS = (float*)(sm + M_BS);
    float* B0 = BS, *B1 = BS + 128, *B2 = BS + 256, *LNg = BS + 320, *LNb = BS + 384;

    int tid = threadIdx.x;
    for (int i = tid; i < 128 * 128; i += 512) {
        int k = i >> 7, n = i & 127;
        W0[k * LDAH + n] = __float2half(w0g[i]);
        W1[k * LDAH + n] = __float2half(w1g[i]);
    }
    for (int i = tid; i < 128 * 64; i += 512) {
        int k = i >> 6, n = i & 63;
        W2[k * 72 + n] = __float2half(w2g[i]);
    }
    if (tid < 128) { B0[tid] = b0g[tid]; B1[tid] = b1g[tid]; }
    if (tid < 64) { B2[tid] = b2g[tid]; LNg[tid] = gg[tid]; LNb[tid] = btg[tid]; }
    __syncthreads();

    int warp = tid >> 5;
    int rt = warp & 3, nh = warp >> 2;
    int r = tid >> 3, seg = tid & 7;  // gather/LN role: 8 threads per row
    int ntiles = (N + 63) >> 6;

    for (int gi = blockIdx.x; gi < ntiles; gi += gridDim.x) {
        int n = (gi << 6) + r;
        bool ok = n < N;
        // ---- Gather: 128 cols (x 64 ++ agg/max(cnt,1) 64) -> half
        {
            float inv = ok ? 1.f / fmaxf(g_cnt[n], 1.f) : 0.f;
            const float4* xp = (const float4*)(x + (size_t)n * 64);
            const float4* ap = (const float4*)(g_agg + (size_t)n * 64);
#pragma unroll
            for (int j = 0; j < 2; j++) {
                int c = seg * 2 + j;  // 8-col chunk, 0..15
                float4 v0, v1;
                if (ok) {
                    if (c < 8) { v0 = __ldg(xp + c * 2); v1 = __ldg(xp + c * 2 + 1); }
                    else {
                        v0 = ap[(c - 8) * 2];
                        v1 = ap[(c - 8) * 2 + 1];
                        v0.x *= inv; v0.y *= inv; v0.z *= inv; v0.w *= inv;
                        v1.x *= inv; v1.y *= inv; v1.z *= inv; v1.w *= inv;
                    }
                } else {
                    v0 = v1 = make_float4(0.f, 0.f, 0.f, 0.f);
                }
                half2 h0 = __floats2half2_rn(v0.x, v0.y);
                half2 h1 = __floats2half2_rn(v0.z, v0.w);
                half2 h2 = __floats2half2_rn(v1.x, v1.y);
                half2 h3 = __floats2half2_rn(v1.z, v1.w);
                *(uint4*)(Ah0 + r * LDAH + c * 8) =
                    make_uint4(h2u(h0), h2u(h1), h2u(h2), h2u(h3));
            }
        }
        __syncthreads();
        mlp_half<1, 2, 8, true>(Ah0, W0, LDAH, B0, Ah1, nullptr, rt, nh);
        __syncthreads();
        mlp_half<1, 2, 8, true>(Ah1, W1, LDAH, B1, Ah0, nullptr, rt, nh);
        __syncthreads();
        mlp_half<1, 1, 8, false>(Ah0, W2, 72, B2, nullptr, F, rt, nh);
        __syncthreads();
        // ---- LayerNorm per row + store (F holds 64x64 post-lrelu)
        {
            float4 v0 = *(float4*)(F + r * LDF2 + seg * 8);
            float4 v1 = *(float4*)(F + r * LDF2 + seg * 8 + 4);
            float s = v0.x + v0.y + v0.z + v0.w + v1.x + v1.y + v1.z + v1.w;
#pragma unroll
            for (int off = 4; off; off >>= 1) s += __shfl_xor_sync(0xffffffffu, s, off);
            float mu = s * (1.f / 64.f);
            float d[8] = {v0.x - mu, v0.y - mu, v0.z - mu, v0.w - mu,
                          v1.x - mu, v1.y - mu, v1.z - mu, v1.w - mu};
            float q = 0.f;
#pragma unroll
            for (int j = 0; j < 8; j++) q += d[j] * d[j];
#pragma unroll
            for (int off = 4; off; off >>= 1) q += __shfl_xor_sync(0xffffffffu, q, off);
            float rs = rsqrtf(q * (1.f / 64.f) + 1e-5f);
            if (ok) {
                int b = seg * 8;
                float4 o0 = make_float4(d[0] * rs * LNg[b + 0] + LNb[b + 0],
                                        d[1] * rs * LNg[b + 1] + LNb[b + 1],
                                        d[2] * rs * LNg[b + 2] + LNb[b + 2],
                                        d[3] * rs * LNg[b + 3] + LNb[b + 3]);
                float4 o1 = make_float4(d[4] * rs * LNg[b + 4] + LNb[b + 4],
                                        d[5] * rs * LNg[b + 5] + LNb[b + 5],
                                        d[6] * rs * LNg[b + 6] + LNb[b + 6],
                                        d[7] * rs * LNg[b + 7] + LNb[b + 7]);
                float4* op = (float4*)(out + (size_t)n * 64 + b);
                op[0] = o0;
                op[1] = o1;
            }
        }
        // no trailing sync (same argument as edge kernel)
    }
}

// ---------------------------------------------------------------------------
extern "C" void kernel_launch(void* const* d_in, const int* in_sizes, int n_in,
                              void* d_out, int out_size) {
    const float* x = (const float*)d_in[0];
    const void* ei = (const void*)d_in[1];
    const float* ea = (const float*)d_in[2];
    const float* m1w0 = (const float*)d_in[5];
    const float* m1b0 = (const float*)d_in[6];
    const float* m1w1 = (const float*)d_in[7];
    const float* m1b1 = (const float*)d_in[8];
    const float* m1w2 = (const float*)d_in[9];
    const float* m1b2 = (const float*)d_in[10];
    const float* ln1g = (const float*)d_in[11];
    const float* ln1b = (const float*)d_in[12];
    const float* m2w0 = (const float*)d_in[13];
    const float* m2b0 = (const float*)d_in[14];
    const float* m2w1 = (const float*)d_in[15];
    const float* m2b1 = (const float*)d_in[16];
    const float* m2w2 = (const float*)d_in[17];
    const float* m2b2 = (const float*)d_in[18];
    const float* ln2g = (const float*)d_in[19];
    const float* ln2b = (const float*)d_in[20];

    int N = in_sizes[0] / 64;
    int E = in_sizes[1] / 2;
    if (N > N_MAX) N = N_MAX;
    if (E > E_MAX) E = E_MAX;
    float* out = (float*)d_out;

    int dev = 0;
    cudaGetDevice(&dev);
    int nsm = 148;
    cudaDeviceGetAttribute(&nsm, cudaDevAttrMultiProcessorCount, dev);

    zero_kernel<<<256, 256>>>(N);
    detect_kernel<<<512, 256>>>((const long long*)ei, E, N);
    convert_kernel<<<512, 256>>>(ei, E, N);

    cudaFuncSetAttribute(edge_tc, cudaFuncAttributeMaxDynamicSharedMemorySize, E_SM);
    cudaFuncSetAttribute(node_tc, cudaFuncAttributeMaxDynamicSharedMemorySize, M_SM);

    edge_tc<<<nsm, 512, E_SM>>>(x, ea, m1w0, m1b0, m1w1, m1b1, m1w2, m1b2,
                                ln1g, ln1b, E);
    node_tc<<<nsm, 512, M_SM>>>(x, m2w0, m2b0, m2w1, m2b1, m2w2, m2b2,
                                ln2g, ln2b, out, N);
}